// round 7
// baseline (speedup 1.0000x reference)
#include <cuda_runtime.h>
#include <cuda_bf16.h>
#include <stdint.h>

// Fixed problem shape: BT=2048, HS=2048, HT=4096, V=32000
#define BTOK 2048
#define VOC  32000
#define HSK  2048
#define HTK  4096

// ---------------------------------------------------------------------------
// Device-global scratch (no cudaMalloc allowed).
// ---------------------------------------------------------------------------
__device__ __nv_bfloat16 g_slog[(size_t)BTOK * VOC];
__device__ __nv_bfloat16 g_tlog[(size_t)BTOK * VOC];
__device__ __nv_bfloat16 g_sa[(size_t)BTOK * HSK];
__device__ __nv_bfloat16 g_sw[(size_t)VOC * HSK];
__device__ __nv_bfloat16 g_ta[(size_t)BTOK * HTK];
__device__ __nv_bfloat16 g_tw[(size_t)VOC * HTK];
__device__ double g_acc[2];          // [0]=hard NLL sum, [1]=JSD sum

// ---------------------------------------------------------------------------
// PTX helpers
// ---------------------------------------------------------------------------
__device__ __forceinline__ uint32_t smem_u32(const void* p) {
    uint32_t a;
    asm("{ .reg .u64 t; cvta.to.shared.u64 t, %1; cvt.u32.u64 %0, t; }" : "=r"(a) : "l"(p));
    return a;
}
__device__ __forceinline__ void cp_async16(uint32_t saddr, const void* gaddr) {
    asm volatile("cp.async.cg.shared.global [%0], [%1], 16;\n" :: "r"(saddr), "l"(gaddr));
}
__device__ __forceinline__ void cpasync_commit() {
    asm volatile("cp.async.commit_group;\n" ::: "memory");
}
#define LDSM_X4(r0, r1, r2, r3, addr) \
    asm volatile("ldmatrix.sync.aligned.m8n8.x4.shared.b16 {%0,%1,%2,%3}, [%4];" \
                 : "=r"(r0), "=r"(r1), "=r"(r2), "=r"(r3) : "r"(addr))

// ---------------------------------------------------------------------------
// Math helpers
// ---------------------------------------------------------------------------
__device__ __forceinline__ float exp_poly(float x) {
    if (fabsf(x) > 0.5f) return __expf(x);
    float p = fmaf(x, 1.f/720.f, 1.f/120.f);
    p = fmaf(x, p, 1.f/24.f);
    p = fmaf(x, p, 1.f/6.f);
    p = fmaf(x, p, 0.5f);
    p = fmaf(x, p, 1.f);
    p = fmaf(x, p, 1.f);
    return p;
}
__device__ __forceinline__ float jsd_term(float s_logit, float t_logit,
                                          float dl, float inv_t) {
    float d = (s_logit - t_logit) - dl;
    float q = exp_poly(t_logit) * inv_t;
    float gg;
    if (fabsf(d) > 0.5f) {
        float ed = __expf(d);
        float c  = __logf(0.5f * (1.f + ed));
        gg = ed * (d - c) - c;
    } else {
        gg = d * d * (0.25f + d * (0.125f + d * (0.03125f + d * (1.f/192.f))));
    }
    return q * gg;
}

// ---------------------------------------------------------------------------
// fp32 -> bf16 conversion: 8 elems/thread (32B read, 16B write).
// which: 0=s_in,1=s_w,2=t_in,3=t_w. n is a multiple of 2048.
// ---------------------------------------------------------------------------
__global__ void __launch_bounds__(256)
convert_kernel(const float* __restrict__ in, int n, int which)
{
    __nv_bfloat16* out = (which == 0) ? g_sa : (which == 1) ? g_sw
                       : (which == 2) ? g_ta : g_tw;
    int i = (blockIdx.x * 256 + threadIdx.x) * 8;
    if (i + 8 <= n) {
        float4 a = *(const float4*)(in + i);
        float4 b = *(const float4*)(in + i + 4);
        uint4 o;
        __nv_bfloat162 p0 = __floats2bfloat162_rn(a.x, a.y);
        __nv_bfloat162 p1 = __floats2bfloat162_rn(a.z, a.w);
        __nv_bfloat162 p2 = __floats2bfloat162_rn(b.x, b.y);
        __nv_bfloat162 p3 = __floats2bfloat162_rn(b.z, b.w);
        o.x = *(uint32_t*)&p0; o.y = *(uint32_t*)&p1;
        o.z = *(uint32_t*)&p2; o.w = *(uint32_t*)&p3;
        *(uint4*)(out + i) = o;
    }
}

// ---------------------------------------------------------------------------
// HMMA GEMM (R4 config — known good): C[bm*128.., bn*128..] (bf16)
//   = A[M,K](bf16) @ W[N,K]^T (bf16)
// 256 threads = 8 warps (2M x 4N), warp tile 64x32, K-stage 64,
// 3-stage cp.async pipeline (32KB/stage), SW128 swizzle, ldmatrix, 2 CTAs/SM.
// ---------------------------------------------------------------------------
static constexpr int GEMM_SMEM = 3 * 32768 + 1024;

__global__ void __launch_bounds__(256, 2)
gemm_hmma_kernel(int K, int V, int which)
{
    const __nv_bfloat16* __restrict__ A = which ? g_ta : g_sa;
    const __nv_bfloat16* __restrict__ W = which ? g_tw : g_sw;
    __nv_bfloat16* __restrict__ C = which ? g_tlog : g_slog;

    extern __shared__ char dynsmem[];
    const uint32_t sbase = (smem_u32(dynsmem) + 1023u) & ~1023u;

    const int tid = threadIdx.x;
    const int bm = blockIdx.x, bn = blockIdx.y;
    const int nc = K >> 6;                       // K / 64

    const int w  = tid >> 5, l = tid & 31;
    const int wm = w >> 2,  wn = w & 3;          // 2 x 4 warp grid
    const int lr = l & 7,   lm = l >> 3;         // ldmatrix lane mapping
    const int g  = l >> 2,  t4 = l & 3;          // mma accumulator mapping

    float acc[4][4][4];
#pragma unroll
    for (int i = 0; i < 4; i++)
#pragma unroll
        for (int j = 0; j < 4; j++)
#pragma unroll
            for (int c = 0; c < 4; c++) acc[i][j][c] = 0.f;

    auto load_stage = [&](int slot, int chunk) {
        const int k0 = chunk << 6;
        const uint32_t sb = sbase + (uint32_t)slot * 32768u;
#pragma unroll
        for (int j = 0; j < 8; j++) {
            int i = tid + j * 256;               // 0..2047
            bool isA = (i < 1024);
            int ii = i & 1023;
            int r = ii >> 3, ck = ii & 7;
            const __nv_bfloat16* gp = isA
                ? (A + (size_t)(bm * 128 + r) * K + k0 + ck * 8)
                : (W + (size_t)(bn * 128 + r) * K + k0 + ck * 8);
            uint32_t so = (isA ? 0u : 16384u) + (uint32_t)(r * 128 + ((ck ^ (r & 7)) << 4));
            cp_async16(sb + so, gp);
        }
    };

    load_stage(0, 0); cpasync_commit();
    load_stage(1, 1); cpasync_commit();

    for (int c = 0; c < nc; c++) {
        if (c + 1 < nc) asm volatile("cp.async.wait_group 1;\n" ::: "memory");
        else            asm volatile("cp.async.wait_group 0;\n" ::: "memory");
        __syncthreads();

        if (c + 2 < nc) { load_stage((c + 2) % 3, c + 2); cpasync_commit(); }

        const uint32_t st = sbase + (uint32_t)(c % 3) * 32768u;

#pragma unroll
        for (int ks = 0; ks < 4; ks++) {
            uint32_t af[4][4];
#pragma unroll
            for (int mt = 0; mt < 4; mt++) {
                int row = wm * 64 + mt * 16 + ((lm & 1) << 3) + lr;
                int ck  = ks * 2 + (lm >> 1);
                uint32_t ad = st + (uint32_t)(row * 128 + ((ck ^ (row & 7)) << 4));
                LDSM_X4(af[mt][0], af[mt][1], af[mt][2], af[mt][3], ad);
            }
            uint32_t bf[2][4];
#pragma unroll
            for (int np = 0; np < 2; np++) {
                int row = wn * 32 + np * 16 + ((lm & 1) << 3) + lr;
                int ck  = ks * 2 + (lm >> 1);
                uint32_t ad = st + 16384u + (uint32_t)(row * 128 + ((ck ^ (row & 7)) << 4));
                LDSM_X4(bf[np][0], bf[np][1], bf[np][2], bf[np][3], ad);
            }
#pragma unroll
            for (int mt = 0; mt < 4; mt++)
#pragma unroll
                for (int nt = 0; nt < 4; nt++) {
                    uint32_t b0 = bf[nt >> 1][nt & 1];
                    uint32_t b1 = bf[nt >> 1][(nt & 1) + 2];
                    asm volatile(
                        "mma.sync.aligned.m16n8k16.row.col.f32.bf16.bf16.f32 "
                        "{%0,%1,%2,%3}, {%4,%5,%6,%7}, {%8,%9}, {%0,%1,%2,%3};\n"
                        : "+f"(acc[mt][nt][0]), "+f"(acc[mt][nt][1]),
                          "+f"(acc[mt][nt][2]), "+f"(acc[mt][nt][3])
                        : "r"(af[mt][0]), "r"(af[mt][1]),
                          "r"(af[mt][2]), "r"(af[mt][3]),
                          "r"(b0), "r"(b1));
                }
        }
    }

#pragma unroll
    for (int mt = 0; mt < 4; mt++) {
        int row = bm * 128 + wm * 64 + mt * 16 + g;
#pragma unroll
        for (int nt = 0; nt < 4; nt++) {
            int col = bn * 128 + wn * 32 + nt * 8 + 2 * t4;
            *(__nv_bfloat162*)(C + (size_t)row * V + col) =
                __floats2bfloat162_rn(acc[mt][nt][0], acc[mt][nt][1]);
            *(__nv_bfloat162*)(C + (size_t)(row + 8) * V + col) =
                __floats2bfloat162_rn(acc[mt][nt][2], acc[mt][nt][3]);
        }
    }
}

// ---------------------------------------------------------------------------
// Fused per-row loss: pass1 sumexp (s,t) + NLL; pass2 JSD (rows L2-resident).
// ---------------------------------------------------------------------------
__global__ void __launch_bounds__(256)
loss_kernel(const int* __restrict__ labels, int V)
{
    const int r = blockIdx.x;
    const __nv_bfloat16* srow = g_slog + (size_t)r * V;
    const __nv_bfloat16* trow = g_tlog + (size_t)r * V;

    __shared__ float red[256];
    __shared__ float s_ls, s_lt, s_inv;

    float ss = 0.f, st = 0.f;
    for (int i = threadIdx.x * 8; i + 8 <= V; i += 256 * 8) {
        uint4 sv = *(const uint4*)(srow + i);
        uint4 tv = *(const uint4*)(trow + i);
        const __nv_bfloat162* sp = (const __nv_bfloat162*)&sv;
        const __nv_bfloat162* tp = (const __nv_bfloat162*)&tv;
#pragma unroll
        for (int j = 0; j < 4; j++) {
            ss += exp_poly(__bfloat162float(sp[j].x)) + exp_poly(__bfloat162float(sp[j].y));
            st += exp_poly(__bfloat162float(tp[j].x)) + exp_poly(__bfloat162float(tp[j].y));
        }
    }
    red[threadIdx.x] = ss;
    __syncthreads();
    for (int o = 128; o > 0; o >>= 1) {
        if (threadIdx.x < o) red[threadIdx.x] += red[threadIdx.x + o];
        __syncthreads();
    }
    float ssum = red[0];
    __syncthreads();
    red[threadIdx.x] = st;
    __syncthreads();
    for (int o = 128; o > 0; o >>= 1) {
        if (threadIdx.x < o) red[threadIdx.x] += red[threadIdx.x + o];
        __syncthreads();
    }
    float tsum = red[0];

    if (threadIdx.x == 0) {
        float ls = logf(ssum);
        float lt = logf(tsum);
        s_ls = ls; s_lt = lt; s_inv = 1.0f / tsum;
        int lab = labels[r];
        if (lab != -100 && lab >= 0 && lab < V) {
            float nll = ls - __bfloat162float(srow[lab]);
            atomicAdd(&g_acc[0], (double)nll);
        }
    }
    __syncthreads();

    const float dl = s_ls - s_lt;
    const float inv_t = s_inv;
    float local = 0.f;
    for (int i = threadIdx.x * 8; i + 8 <= V; i += 256 * 8) {
        uint4 sv = *(const uint4*)(srow + i);
        uint4 tv = *(const uint4*)(trow + i);
        const __nv_bfloat162* sp = (const __nv_bfloat162*)&sv;
        const __nv_bfloat162* tp = (const __nv_bfloat162*)&tv;
#pragma unroll
        for (int j = 0; j < 4; j++) {
            local += jsd_term(__bfloat162float(sp[j].x), __bfloat162float(tp[j].x), dl, inv_t);
            local += jsd_term(__bfloat162float(sp[j].y), __bfloat162float(tp[j].y), dl, inv_t);
        }
    }
    __syncthreads();
    red[threadIdx.x] = local;
    __syncthreads();
    for (int o = 128; o > 0; o >>= 1) {
        if (threadIdx.x < o) red[threadIdx.x] += red[threadIdx.x + o];
        __syncthreads();
    }
    if (threadIdx.x == 0) atomicAdd(&g_acc[1], (double)red[0]);
}

__global__ void zero_kernel() {
    if (threadIdx.x == 0) { g_acc[0] = 0.0; g_acc[1] = 0.0; }
}

__global__ void finalize_kernel(float* out, int BT) {
    if (threadIdx.x == 0) {
        double hard = g_acc[0] / (double)BT;
        double soft = 0.5 * (g_acc[1] / (double)BT);
        out[0] = (float)(0.5 * hard + 0.5 * soft);
    }
}

// ---------------------------------------------------------------------------
// Launch: fork/join side stream so the teacher converts (DRAM-bound) overlap
// with the student GEMM (compute-bound). Stream/events created lazily on the
// first (uncaptured) call; record/wait are graph-capturable ops.
// ---------------------------------------------------------------------------
extern "C" void kernel_launch(void* const* d_in, const int* in_sizes, int n_in,
                              void* d_out, int out_size)
{
    const float* s_in   = (const float*)d_in[0];
    const float* s_w    = (const float*)d_in[1];
    const float* t_in   = (const float*)d_in[2];
    const float* t_w    = (const float*)d_in[3];
    const int*   labels = (const int*)d_in[4];

    const int BT = in_sizes[4];
    const int HS = in_sizes[0] / BT;
    const int HT = in_sizes[2] / BT;
    const int V  = in_sizes[1] / HS;

    static cudaStream_t side = nullptr;
    static cudaEvent_t ev_fork = nullptr, ev_join = nullptr;
    static bool init_done = false;
    if (!init_done) {
        cudaStreamCreateWithFlags(&side, cudaStreamNonBlocking);
        cudaEventCreateWithFlags(&ev_fork, cudaEventDisableTiming);
        cudaEventCreateWithFlags(&ev_join, cudaEventDisableTiming);
        cudaFuncSetAttribute(gemm_hmma_kernel,
                             cudaFuncAttributeMaxDynamicSharedMemorySize, GEMM_SMEM);
        init_done = true;
    }

    zero_kernel<<<1, 32>>>();

    // Student converts on the main stream.
    convert_kernel<<<in_sizes[0] / 2048, 256>>>(s_in, in_sizes[0], 0);
    convert_kernel<<<in_sizes[1] / 2048, 256>>>(s_w,  in_sizes[1], 1);

    // Fork: teacher converts on the side stream, overlapping the student GEMM.
    cudaEventRecord(ev_fork, 0);
    cudaStreamWaitEvent(side, ev_fork, 0);
    convert_kernel<<<in_sizes[2] / 2048, 256, 0, side>>>(t_in, in_sizes[2], 2);
    convert_kernel<<<in_sizes[3] / 2048, 256, 0, side>>>(t_w,  in_sizes[3], 3);
    cudaEventRecord(ev_join, side);

    dim3 gg(BT / 128, V / 128);
    gemm_hmma_kernel<<<gg, 256, GEMM_SMEM>>>(HS, V, 0);

    // Join: teacher GEMM needs teacher bf16 operands.
    cudaStreamWaitEvent(0, ev_join, 0);
    gemm_hmma_kernel<<<gg, 256, GEMM_SMEM>>>(HT, V, 1);

    loss_kernel<<<BT, 256>>>(labels, V);

    finalize_kernel<<<1, 32>>>((float*)d_out, BT);
}

// round 8
// speedup vs baseline: 1.5216x; 1.5216x over previous
#include <cuda_runtime.h>
#include <cuda_bf16.h>
#include <stdint.h>

// Fixed problem shape: BT=2048, HS=2048, HT=4096, V=32000
#define BTOK 2048
#define VOC  32000
#define HSK  2048
#define HTK  4096

// ---------------------------------------------------------------------------
// Device-global scratch (no cudaMalloc allowed).
// ---------------------------------------------------------------------------
__device__ __nv_bfloat16 g_slog[(size_t)BTOK * VOC];
__device__ __nv_bfloat16 g_tlog[(size_t)BTOK * VOC];
__device__ __nv_bfloat16 g_sa[(size_t)BTOK * HSK];
__device__ __nv_bfloat16 g_sw[(size_t)VOC * HSK];
__device__ __nv_bfloat16 g_ta[(size_t)BTOK * HTK];
__device__ __nv_bfloat16 g_tw[(size_t)VOC * HTK];
__device__ double g_acc[2];          // [0]=hard NLL sum, [1]=JSD sum

// ---------------------------------------------------------------------------
// PTX helpers
// ---------------------------------------------------------------------------
__device__ __forceinline__ uint32_t smem_u32(const void* p) {
    uint32_t a;
    asm("{ .reg .u64 t; cvta.to.shared.u64 t, %1; cvt.u32.u64 %0, t; }" : "=r"(a) : "l"(p));
    return a;
}
__device__ __forceinline__ void cp_async16(uint32_t saddr, const void* gaddr) {
    asm volatile("cp.async.cg.shared.global [%0], [%1], 16;\n" :: "r"(saddr), "l"(gaddr));
}
__device__ __forceinline__ void cpasync_commit() {
    asm volatile("cp.async.commit_group;\n" ::: "memory");
}
#define LDSM_X4(r0, r1, r2, r3, addr) \
    asm volatile("ldmatrix.sync.aligned.m8n8.x4.shared.b16 {%0,%1,%2,%3}, [%4];" \
                 : "=r"(r0), "=r"(r1), "=r"(r2), "=r"(r3) : "r"(addr))

// ---------------------------------------------------------------------------
// Math helpers
// ---------------------------------------------------------------------------
__device__ __forceinline__ float exp_poly(float x) {
    if (fabsf(x) > 0.5f) return __expf(x);
    float p = fmaf(x, 1.f/720.f, 1.f/120.f);
    p = fmaf(x, p, 1.f/24.f);
    p = fmaf(x, p, 1.f/6.f);
    p = fmaf(x, p, 0.5f);
    p = fmaf(x, p, 1.f);
    p = fmaf(x, p, 1.f);
    return p;
}
__device__ __forceinline__ float jsd_term(float s_logit, float t_logit,
                                          float dl, float inv_t) {
    float d = (s_logit - t_logit) - dl;
    float q = exp_poly(t_logit) * inv_t;
    float gg;
    if (fabsf(d) > 0.5f) {
        float ed = __expf(d);
        float c  = __logf(0.5f * (1.f + ed));
        gg = ed * (d - c) - c;
    } else {
        gg = d * d * (0.25f + d * (0.125f + d * (0.03125f + d * (1.f/192.f))));
    }
    return q * gg;
}

// ---------------------------------------------------------------------------
// fp32 -> bf16 conversion: 8 elems/thread (32B read, 16B write).
// which: 0=s_in,1=s_w,2=t_in,3=t_w. n is a multiple of 2048.
// ---------------------------------------------------------------------------
__global__ void __launch_bounds__(256)
convert_kernel(const float* __restrict__ in, int n, int which)
{
    __nv_bfloat16* out = (which == 0) ? g_sa : (which == 1) ? g_sw
                       : (which == 2) ? g_ta : g_tw;
    int i = (blockIdx.x * 256 + threadIdx.x) * 8;
    if (i + 8 <= n) {
        float4 a = *(const float4*)(in + i);
        float4 b = *(const float4*)(in + i + 4);
        uint4 o;
        __nv_bfloat162 p0 = __floats2bfloat162_rn(a.x, a.y);
        __nv_bfloat162 p1 = __floats2bfloat162_rn(a.z, a.w);
        __nv_bfloat162 p2 = __floats2bfloat162_rn(b.x, b.y);
        __nv_bfloat162 p3 = __floats2bfloat162_rn(b.z, b.w);
        o.x = *(uint32_t*)&p0; o.y = *(uint32_t*)&p1;
        o.z = *(uint32_t*)&p2; o.w = *(uint32_t*)&p3;
        *(uint4*)(out + i) = o;
    }
}

// ---------------------------------------------------------------------------
// HMMA GEMM (R4 config — known good): C[bm*128.., bn*128..] (bf16)
//   = A[M,K](bf16) @ W[N,K]^T (bf16)
// 256 threads = 8 warps (2M x 4N), warp tile 64x32, K-stage 64,
// 3-stage cp.async pipeline (32KB/stage), SW128 swizzle, ldmatrix, 2 CTAs/SM.
// ---------------------------------------------------------------------------
static constexpr int GEMM_SMEM = 3 * 32768 + 1024;

__global__ void __launch_bounds__(256, 2)
gemm_hmma_kernel(int K, int V, int which)
{
    const __nv_bfloat16* __restrict__ A = which ? g_ta : g_sa;
    const __nv_bfloat16* __restrict__ W = which ? g_tw : g_sw;
    __nv_bfloat16* __restrict__ C = which ? g_tlog : g_slog;

    extern __shared__ char dynsmem[];
    const uint32_t sbase = (smem_u32(dynsmem) + 1023u) & ~1023u;

    const int tid = threadIdx.x;
    const int bm = blockIdx.x, bn = blockIdx.y;
    const int nc = K >> 6;                       // K / 64

    const int w  = tid >> 5, l = tid & 31;
    const int wm = w >> 2,  wn = w & 3;          // 2 x 4 warp grid
    const int lr = l & 7,   lm = l >> 3;         // ldmatrix lane mapping
    const int g  = l >> 2,  t4 = l & 3;          // mma accumulator mapping

    float acc[4][4][4];
#pragma unroll
    for (int i = 0; i < 4; i++)
#pragma unroll
        for (int j = 0; j < 4; j++)
#pragma unroll
            for (int c = 0; c < 4; c++) acc[i][j][c] = 0.f;

    auto load_stage = [&](int slot, int chunk) {
        const int k0 = chunk << 6;
        const uint32_t sb = sbase + (uint32_t)slot * 32768u;
#pragma unroll
        for (int j = 0; j < 8; j++) {
            int i = tid + j * 256;               // 0..2047
            bool isA = (i < 1024);
            int ii = i & 1023;
            int r = ii >> 3, ck = ii & 7;
            const __nv_bfloat16* gp = isA
                ? (A + (size_t)(bm * 128 + r) * K + k0 + ck * 8)
                : (W + (size_t)(bn * 128 + r) * K + k0 + ck * 8);
            uint32_t so = (isA ? 0u : 16384u) + (uint32_t)(r * 128 + ((ck ^ (r & 7)) << 4));
            cp_async16(sb + so, gp);
        }
    };

    load_stage(0, 0); cpasync_commit();
    load_stage(1, 1); cpasync_commit();

    for (int c = 0; c < nc; c++) {
        if (c + 1 < nc) asm volatile("cp.async.wait_group 1;\n" ::: "memory");
        else            asm volatile("cp.async.wait_group 0;\n" ::: "memory");
        __syncthreads();

        if (c + 2 < nc) { load_stage((c + 2) % 3, c + 2); cpasync_commit(); }

        const uint32_t st = sbase + (uint32_t)(c % 3) * 32768u;

#pragma unroll
        for (int ks = 0; ks < 4; ks++) {
            uint32_t af[4][4];
#pragma unroll
            for (int mt = 0; mt < 4; mt++) {
                int row = wm * 64 + mt * 16 + ((lm & 1) << 3) + lr;
                int ck  = ks * 2 + (lm >> 1);
                uint32_t ad = st + (uint32_t)(row * 128 + ((ck ^ (row & 7)) << 4));
                LDSM_X4(af[mt][0], af[mt][1], af[mt][2], af[mt][3], ad);
            }
            uint32_t bf[2][4];
#pragma unroll
            for (int np = 0; np < 2; np++) {
                int row = wn * 32 + np * 16 + ((lm & 1) << 3) + lr;
                int ck  = ks * 2 + (lm >> 1);
                uint32_t ad = st + 16384u + (uint32_t)(row * 128 + ((ck ^ (row & 7)) << 4));
                LDSM_X4(bf[np][0], bf[np][1], bf[np][2], bf[np][3], ad);
            }
#pragma unroll
            for (int mt = 0; mt < 4; mt++)
#pragma unroll
                for (int nt = 0; nt < 4; nt++) {
                    uint32_t b0 = bf[nt >> 1][nt & 1];
                    uint32_t b1 = bf[nt >> 1][(nt & 1) + 2];
                    asm volatile(
                        "mma.sync.aligned.m16n8k16.row.col.f32.bf16.bf16.f32 "
                        "{%0,%1,%2,%3}, {%4,%5,%6,%7}, {%8,%9}, {%0,%1,%2,%3};\n"
                        : "+f"(acc[mt][nt][0]), "+f"(acc[mt][nt][1]),
                          "+f"(acc[mt][nt][2]), "+f"(acc[mt][nt][3])
                        : "r"(af[mt][0]), "r"(af[mt][1]),
                          "r"(af[mt][2]), "r"(af[mt][3]),
                          "r"(b0), "r"(b1));
                }
        }
    }

#pragma unroll
    for (int mt = 0; mt < 4; mt++) {
        int row = bm * 128 + wm * 64 + mt * 16 + g;
#pragma unroll
        for (int nt = 0; nt < 4; nt++) {
            int col = bn * 128 + wn * 32 + nt * 8 + 2 * t4;
            *(__nv_bfloat162*)(C + (size_t)row * V + col) =
                __floats2bfloat162_rn(acc[mt][nt][0], acc[mt][nt][1]);
            *(__nv_bfloat162*)(C + (size_t)(row + 8) * V + col) =
                __floats2bfloat162_rn(acc[mt][nt][2], acc[mt][nt][3]);
        }
    }
}

// ---------------------------------------------------------------------------
// Fused per-row loss: pass1 sumexp (s,t) + NLL; pass2 JSD (rows L2-resident).
// ---------------------------------------------------------------------------
__global__ void __launch_bounds__(256)
loss_kernel(const int* __restrict__ labels, int V)
{
    const int r = blockIdx.x;
    const __nv_bfloat16* srow = g_slog + (size_t)r * V;
    const __nv_bfloat16* trow = g_tlog + (size_t)r * V;

    __shared__ float red[256];
    __shared__ float s_ls, s_lt, s_inv;

    float ss = 0.f, st = 0.f;
    for (int i = threadIdx.x * 8; i + 8 <= V; i += 256 * 8) {
        uint4 sv = *(const uint4*)(srow + i);
        uint4 tv = *(const uint4*)(trow + i);
        const __nv_bfloat162* sp = (const __nv_bfloat162*)&sv;
        const __nv_bfloat162* tp = (const __nv_bfloat162*)&tv;
#pragma unroll
        for (int j = 0; j < 4; j++) {
            ss += exp_poly(__bfloat162float(sp[j].x)) + exp_poly(__bfloat162float(sp[j].y));
            st += exp_poly(__bfloat162float(tp[j].x)) + exp_poly(__bfloat162float(tp[j].y));
        }
    }
    red[threadIdx.x] = ss;
    __syncthreads();
    for (int o = 128; o > 0; o >>= 1) {
        if (threadIdx.x < o) red[threadIdx.x] += red[threadIdx.x + o];
        __syncthreads();
    }
    float ssum = red[0];
    __syncthreads();
    red[threadIdx.x] = st;
    __syncthreads();
    for (int o = 128; o > 0; o >>= 1) {
        if (threadIdx.x < o) red[threadIdx.x] += red[threadIdx.x + o];
        __syncthreads();
    }
    float tsum = red[0];

    if (threadIdx.x == 0) {
        float ls = logf(ssum);
        float lt = logf(tsum);
        s_ls = ls; s_lt = lt; s_inv = 1.0f / tsum;
        int lab = labels[r];
        if (lab != -100 && lab >= 0 && lab < V) {
            float nll = ls - __bfloat162float(srow[lab]);
            atomicAdd(&g_acc[0], (double)nll);
        }
    }
    __syncthreads();

    const float dl = s_ls - s_lt;
    const float inv_t = s_inv;
    float local = 0.f;
    for (int i = threadIdx.x * 8; i + 8 <= V; i += 256 * 8) {
        uint4 sv = *(const uint4*)(srow + i);
        uint4 tv = *(const uint4*)(trow + i);
        const __nv_bfloat162* sp = (const __nv_bfloat162*)&sv;
        const __nv_bfloat162* tp = (const __nv_bfloat162*)&tv;
#pragma unroll
        for (int j = 0; j < 4; j++) {
            local += jsd_term(__bfloat162float(sp[j].x), __bfloat162float(tp[j].x), dl, inv_t);
            local += jsd_term(__bfloat162float(sp[j].y), __bfloat162float(tp[j].y), dl, inv_t);
        }
    }
    __syncthreads();
    red[threadIdx.x] = local;
    __syncthreads();
    for (int o = 128; o > 0; o >>= 1) {
        if (threadIdx.x < o) red[threadIdx.x] += red[threadIdx.x + o];
        __syncthreads();
    }
    if (threadIdx.x == 0) atomicAdd(&g_acc[1], (double)red[0]);
}

__global__ void zero_kernel() {
    if (threadIdx.x == 0) { g_acc[0] = 0.0; g_acc[1] = 0.0; }
}

__global__ void finalize_kernel(float* out, int BT) {
    if (threadIdx.x == 0) {
        double hard = g_acc[0] / (double)BT;
        double soft = 0.5 * (g_acc[1] / (double)BT);
        out[0] = (float)(0.5 * hard + 0.5 * soft);
    }
}

// ---------------------------------------------------------------------------
// Launch: fork/join side stream so the teacher converts (DRAM-bound) overlap
// with the student GEMM (compute-bound). Stream/events created lazily on the
// first (uncaptured) call; record/wait are graph-capturable ops.
// ---------------------------------------------------------------------------
extern "C" void kernel_launch(void* const* d_in, const int* in_sizes, int n_in,
                              void* d_out, int out_size)
{
    const float* s_in   = (const float*)d_in[0];
    const float* s_w    = (const float*)d_in[1];
    const float* t_in   = (const float*)d_in[2];
    const float* t_w    = (const float*)d_in[3];
    const int*   labels = (const int*)d_in[4];

    const int BT = in_sizes[4];
    const int HS = in_sizes[0] / BT;
    const int HT = in_sizes[2] / BT;
    const int V  = in_sizes[1] / HS;

    static cudaStream_t side = nullptr;
    static cudaEvent_t ev_fork = nullptr, ev_join = nullptr;
    static bool init_done = false;
    if (!init_done) {
        cudaStreamCreateWithFlags(&side, cudaStreamNonBlocking);
        cudaEventCreateWithFlags(&ev_fork, cudaEventDisableTiming);
        cudaEventCreateWithFlags(&ev_join, cudaEventDisableTiming);
        cudaFuncSetAttribute(gemm_hmma_kernel,
                             cudaFuncAttributeMaxDynamicSharedMemorySize, GEMM_SMEM);
        init_done = true;
    }

    zero_kernel<<<1, 32>>>();

    // Student converts on the main stream.
    convert_kernel<<<in_sizes[0] / 2048, 256>>>(s_in, in_sizes[0], 0);
    convert_kernel<<<in_sizes[1] / 2048, 256>>>(s_w,  in_sizes[1], 1);

    // Fork: teacher converts on the side stream, overlapping the student GEMM.
    cudaEventRecord(ev_fork, 0);
    cudaStreamWaitEvent(side, ev_fork, 0);
    convert_kernel<<<in_sizes[2] / 2048, 256, 0, side>>>(t_in, in_sizes[2], 2);
    convert_kernel<<<in_sizes[3] / 2048, 256, 0, side>>>(t_w,  in_sizes[3], 3);
    cudaEventRecord(ev_join, side);

    dim3 gg(BT / 128, V / 128);
    gemm_hmma_kernel<<<gg, 256, GEMM_SMEM>>>(HS, V, 0);

    // Join: teacher GEMM needs teacher bf16 operands.
    cudaStreamWaitEvent(0, ev_join, 0);
    gemm_hmma_kernel<<<gg, 256, GEMM_SMEM>>>(HT, V, 1);

    loss_kernel<<<BT, 256>>>(labels, V);

    finalize_kernel<<<1, 32>>>((float*)d_out, BT);
}